// round 1
// baseline (speedup 1.0000x reference)
#include <cuda_runtime.h>
#include <cuda_bf16.h>
#include <math.h>

// Shapes fixed by the reference problem.
#define BB 8
#define TT 256
#define UU 65
#define UL 64          // U - 1
#define VV 1024

// Scratch (device globals — no allocation allowed).
__device__ float g_lp_blank[BB * TT * UU];   // lp_blank[b][t][u]
__device__ float g_lp_label[BB * TT * UL];   // lp_label[b][t][u], u < U-1
__device__ float g_ll[BB];                   // per-batch log-likelihood

__device__ __forceinline__ float warpReduceMax(float v) {
#pragma unroll
    for (int o = 16; o > 0; o >>= 1)
        v = fmaxf(v, __shfl_xor_sync(0xffffffffu, v, o));
    return v;
}
__device__ __forceinline__ float warpReduceSum(float v) {
#pragma unroll
    for (int o = 16; o > 0; o >>= 1)
        v += __shfl_xor_sync(0xffffffffu, v, o);
    return v;
}

// Kernel 1: per (b,t,u) row of V=1024 floats, compute logsumexp and emit
// lp_blank = acts[...,0] - lse, lp_label = acts[...,label] - lse.
// 256 threads/block, each thread holds one float4 -> whole row in registers,
// single pass over HBM.
__global__ void __launch_bounds__(256) lse_kernel(const float* __restrict__ acts,
                                                  const int* __restrict__ labels) {
    const int row = blockIdx.x;              // row = (b*TT + t)*UU + u
    const int u  = row % UU;
    const int bt = row / UU;
    const int t  = bt % TT;
    const int b  = bt / TT;

    const int tid  = threadIdx.x;
    const int lane = tid & 31;
    const int wid  = tid >> 5;

    const float4* a4 = reinterpret_cast<const float4*>(acts + (size_t)row * VV);
    float4 v = a4[tid];

    __shared__ float smax[8];
    __shared__ float ssum[8];
    __shared__ float sred;
    __shared__ float slab;

    // --- max reduction ---
    float m = fmaxf(fmaxf(v.x, v.y), fmaxf(v.z, v.w));
    m = warpReduceMax(m);
    if (lane == 0) smax[wid] = m;
    __syncthreads();
    if (wid == 0) {
        float mm = (lane < 8) ? smax[lane] : -INFINITY;
        mm = warpReduceMax(mm);
        if (lane == 0) sred = mm;
    }
    __syncthreads();
    const float bm = sred;

    // --- label value pickup (register -> shared) ---
    int lab = -1;
    if (u < UL) lab = labels[b * UL + u];
    if (lab >= 0) {
        const int base = tid * 4;
        if (lab >= base && lab < base + 4) {
            float lv = (lab == base)     ? v.x
                     : (lab == base + 1) ? v.y
                     : (lab == base + 2) ? v.z : v.w;
            slab = lv;
        }
    }

    // --- sum(exp) reduction ---
    float s = __expf(v.x - bm) + __expf(v.y - bm) + __expf(v.z - bm) + __expf(v.w - bm);
    s = warpReduceSum(s);
    if (lane == 0) ssum[wid] = s;
    __syncthreads();

    if (tid == 0) {
        float tot = 0.f;
#pragma unroll
        for (int i = 0; i < 8; ++i) tot += ssum[i];
        const float lse = bm + __logf(tot);
        g_lp_blank[row] = v.x - lse;   // element 0 of the row lives in thread 0's v.x
        if (lab >= 0) g_lp_label[(b * TT + t) * UL + u] = slab - lse;
    }
}

__device__ __forceinline__ float logaddexpf_(float a, float b) {
    float m = fmaxf(a, b);
    float d = fminf(a, b) - m;
    return m + log1pf(__expf(d));
}

// Kernel 2: anti-diagonal wavefront over the T x U alpha grid, one CTA per batch.
// lp tables preloaded into dynamic shared memory; two rolling diagonal buffers.
__global__ void __launch_bounds__(128) alpha_kernel(const int* __restrict__ act_lens,
                                                    const int* __restrict__ label_lens) {
    extern __shared__ float sm[];
    float* s_blank = sm;                        // TT*UU
    float* s_label = s_blank + TT * UU;         // TT*UL
    float* dA      = s_label + TT * UL;         // UU
    float* dB      = dA + UU;                   // UU
    __shared__ float s_target;

    const int b   = blockIdx.x;
    const int tid = threadIdx.x;

    for (int i = tid; i < TT * UU; i += blockDim.x)
        s_blank[i] = g_lp_blank[b * TT * UU + i];
    for (int i = tid; i < TT * UL; i += blockDim.x)
        s_label[i] = g_lp_label[b * TT * UL + i];

    const int t_tgt = act_lens[b] - 1;
    const int u_tgt = label_lens[b];
    __syncthreads();

    float* prev = dA;
    float* cur  = dB;
    const int u = tid;

    for (int d = 0; d < TT + UU - 1; ++d) {
        if (u < UU) {
            const int t = d - u;
            if (t >= 0 && t < TT) {
                float a;
                if (t == 0) {
                    a = (u == 0) ? 0.f : prev[u - 1] + s_label[u - 1];
                } else if (u == 0) {
                    a = prev[0] + s_blank[(t - 1) * UU];
                } else {
                    a = logaddexpf_(prev[u]     + s_blank[(t - 1) * UU + u],
                                    prev[u - 1] + s_label[t * UL + (u - 1)]);
                }
                cur[u] = a;
                if (t == t_tgt && u == u_tgt)
                    s_target = a + s_blank[t * UU + u];
            }
        }
        __syncthreads();
        float* tmp = prev; prev = cur; cur = tmp;
    }

    if (tid == 0) g_ll[b] = s_target;
}

// Kernel 3: deterministic finalize.
__global__ void finalize_kernel(float* __restrict__ out) {
    if (threadIdx.x == 0 && blockIdx.x == 0) {
        float s = 0.f;
#pragma unroll
        for (int i = 0; i < BB; ++i) s += g_ll[i];
        out[0] = -s / (float)BB;
    }
}

extern "C" void kernel_launch(void* const* d_in, const int* in_sizes, int n_in,
                              void* d_out, int out_size) {
    const float* acts       = (const float*)d_in[0];
    const int*   labels     = (const int*)d_in[1];
    const int*   act_lens   = (const int*)d_in[2];
    const int*   label_lens = (const int*)d_in[3];
    float* out = (float*)d_out;

    const int smem_alpha = (TT * UU + TT * UL + 2 * UU) * (int)sizeof(float);
    cudaFuncSetAttribute(alpha_kernel, cudaFuncAttributeMaxDynamicSharedMemorySize, smem_alpha);

    lse_kernel<<<BB * TT * UU, 256>>>(acts, labels);
    alpha_kernel<<<BB, 128, smem_alpha>>>(act_lens, label_lens);
    finalize_kernel<<<1, 32>>>(out);
}

// round 3
// speedup vs baseline: 1.2308x; 1.2308x over previous
#include <cuda_runtime.h>
#include <cuda_bf16.h>
#include <math.h>

#define BB 8
#define TT 256
#define UU 65
#define UL 64
#define VV 1024
#define SB 66   // padded smem row stride (floats) -> 2-way max bank conflict on diagonals

__device__ float g_lp_blank[BB * TT * UU];
__device__ float g_lp_label[BB * TT * UL];
__device__ float g_ll[BB];

__device__ __forceinline__ float warpMax(float v) {
#pragma unroll
    for (int o = 16; o > 0; o >>= 1) v = fmaxf(v, __shfl_xor_sync(0xffffffffu, v, o));
    return v;
}
__device__ __forceinline__ float warpSum(float v) {
#pragma unroll
    for (int o = 16; o > 0; o >>= 1) v += __shfl_xor_sync(0xffffffffu, v, o);
    return v;
}

// ---------------- Kernel 1: warp-per-row logsumexp ----------------
// Row = (b*TT + t)*UU + u of V=1024 floats. Lane loads 8 float4 (MLP=8),
// warp-shuffle reductions only. One LDG pass over 545 MB => DRAM-bound.
__global__ void __launch_bounds__(256) lse_kernel(const float* __restrict__ acts,
                                                  const int* __restrict__ labels) {
    const int row  = blockIdx.x * 8 + (threadIdx.x >> 5);
    const int lane = threadIdx.x & 31;

    const int u  = row % UU;
    const int bt = row / UU;
    const int b  = bt / TT;

    const float4* a4 = reinterpret_cast<const float4*>(acts + (size_t)row * VV);
    float4 v[8];
#pragma unroll
    for (int j = 0; j < 8; ++j) v[j] = a4[lane + 32 * j];

    // max
    float m = -INFINITY;
#pragma unroll
    for (int j = 0; j < 8; ++j)
        m = fmaxf(m, fmaxf(fmaxf(v[j].x, v[j].y), fmaxf(v[j].z, v[j].w)));
    m = warpMax(m);

    // sum of exp
    float s = 0.f;
#pragma unroll
    for (int j = 0; j < 8; ++j)
        s += __expf(v[j].x - m) + __expf(v[j].y - m) + __expf(v[j].z - m) + __expf(v[j].w - m);
    s = warpSum(s);
    const float lse = m + __logf(s);

    // label value: lab uniform across the warp; owner lane picks, broadcast.
    if (u < UL) {
        const int lab = labels[b * UL + u];
        const int q = lab >> 2, c = lab & 3, jj = q >> 5;
        float cand = 0.f;
#pragma unroll
        for (int j = 0; j < 8; ++j) {
            if (j == jj) {
                float4 f = v[j];
                cand = (c == 0) ? f.x : (c == 1) ? f.y : (c == 2) ? f.z : f.w;
            }
        }
        const float lv = __shfl_sync(0xffffffffu, cand, q & 31);
        if (lane == 0) g_lp_label[bt * UL + u] = lv - lse;
    }
    if (lane == 0) g_lp_blank[row] = v[0].x - lse;   // lane 0 holds element 0
}

__device__ __forceinline__ float lae(float a, float b) {
    float m = fmaxf(a, b);
    float d = fminf(a, b) - m;
    return m + __logf(1.f + __expf(d));
}

// ---------------- Kernel 2: single-warp wavefront DP ----------------
// 256 threads preload lp tables to padded smem; warps 1..7 exit; warp 0 runs
// 319 diagonals fully in registers with ONE shfl_up per diagonal, no barriers.
__global__ void __launch_bounds__(256) alpha_kernel(const int* __restrict__ act_lens,
                                                    const int* __restrict__ label_lens) {
    extern __shared__ float sm[];
    float* s_blank = sm;                 // TT * SB (uses 65 of 66 per row)
    float* s_label = sm + TT * SB;       // TT * SB (uses 64 of 66 per row)

    const int b    = blockIdx.x;
    const int tid  = threadIdx.x;
    const int lane = tid & 31;
    const int wid  = tid >> 5;

    // preload (coalesced per t-row); NOTE: 65 blank entries per row (0..64)
    for (int t = wid; t < TT; t += 8) {
        const float* gb = g_lp_blank + ((size_t)b * TT + t) * UU;
        const float* gl = g_lp_label + ((size_t)b * TT + t) * UL;
        s_blank[t * SB + lane]      = gb[lane];
        s_blank[t * SB + 32 + lane] = gb[32 + lane];        // 32..63
        if (lane == 0) s_blank[t * SB + 64] = gb[64];       // 64
        s_label[t * SB + lane]      = gl[lane];
        s_label[t * SB + 32 + lane] = gl[32 + lane];
    }
    __syncthreads();
    if (wid != 0) return;

    const int t_tgt = act_lens[b] - 1;
    const int u_tgt = label_lens[b];
    const int d_tgt = t_tgt + u_tgt;

    const int u0 = 2 * lane, u1 = 2 * lane + 1;
    float a0 = 0.f, a1 = 0.f, a2 = 0.f;   // alpha[u0], alpha[u1], (lane31) alpha[64]
    float tgt = 0.f;

#pragma unroll 1
    for (int d = 0; d < TT + UU - 1; ++d) {
        const float p_um1 = __shfl_up_sync(0xffffffffu, a1, 1); // prev[u0-1]
        const int t0 = d - u0, t1 = d - u1, t2 = d - 64;
        float n0 = a0, n1 = a1, n2 = a2;

        if (t0 >= 0 && t0 < TT) {
            if (u0 == 0)      n0 = (t0 == 0) ? 0.f : a0 + s_blank[(t0 - 1) * SB];
            else if (t0 == 0) n0 = p_um1 + s_label[u0 - 1];
            else              n0 = lae(a0 + s_blank[(t0 - 1) * SB + u0],
                                       p_um1 + s_label[t0 * SB + u0 - 1]);
            if (d == d_tgt && u0 == u_tgt) tgt = n0 + s_blank[t0 * SB + u0];
        }
        if (t1 >= 0 && t1 < TT) {
            if (t1 == 0) n1 = a0 + s_label[u1 - 1];
            else         n1 = lae(a1 + s_blank[(t1 - 1) * SB + u1],
                                  a0 + s_label[t1 * SB + u1 - 1]);
            if (d == d_tgt && u1 == u_tgt) tgt = n1 + s_blank[t1 * SB + u1];
        }
        if (lane == 31 && t2 >= 0 && t2 < TT) {
            n2 = (t2 == 0) ? a1 + s_label[63]
                           : lae(a2 + s_blank[(t2 - 1) * SB + 64],
                                 a1 + s_label[t2 * SB + 63]);
            if (d == d_tgt && 64 == u_tgt) tgt = n2 + s_blank[t2 * SB + 64];
        }
        a0 = n0; a1 = n1; a2 = n2;
    }

    const int owner = (u_tgt == 64) ? 31 : (u_tgt >> 1);
    const float ll = __shfl_sync(0xffffffffu, tgt, owner);
    if (lane == 0) g_ll[b] = ll;
}

// ---------------- Kernel 3: finalize ----------------
__global__ void finalize_kernel(float* __restrict__ out) {
    if (threadIdx.x == 0 && blockIdx.x == 0) {
        float s = 0.f;
#pragma unroll
        for (int i = 0; i < BB; ++i) s += g_ll[i];
        out[0] = -s / (float)BB;
    }
}

extern "C" void kernel_launch(void* const* d_in, const int* in_sizes, int n_in,
                              void* d_out, int out_size) {
    const float* acts       = (const float*)d_in[0];
    const int*   labels     = (const int*)d_in[1];
    const int*   act_lens   = (const int*)d_in[2];
    const int*   label_lens = (const int*)d_in[3];
    float* out = (float*)d_out;

    const int smem_alpha = 2 * TT * SB * (int)sizeof(float);
    cudaFuncSetAttribute(alpha_kernel, cudaFuncAttributeMaxDynamicSharedMemorySize, smem_alpha);

    const int rows = BB * TT * UU;                 // 133120 = 8 warps * 16640 blocks
    lse_kernel<<<rows / 8, 256>>>(acts, labels);
    alpha_kernel<<<BB, 256, smem_alpha>>>(act_lens, label_lens);
    finalize_kernel<<<1, 32>>>(out);
}

// round 4
// speedup vs baseline: 1.9490x; 1.5834x over previous
#include <cuda_runtime.h>
#include <cuda_bf16.h>
#include <math.h>

#define BB 8
#define TT 256
#define UU 65
#define UL 64
#define VV 1024
#define SB 66            // padded smem row stride
#define NEG_BIG (-1e30f)

__device__ float g_lp_blank[BB * TT * UU];
__device__ float g_lp_label[BB * TT * UL];
__device__ float g_ll[BB];

__device__ __forceinline__ float warpMax(float v) {
#pragma unroll
    for (int o = 16; o > 0; o >>= 1) v = fmaxf(v, __shfl_xor_sync(0xffffffffu, v, o));
    return v;
}
__device__ __forceinline__ float warpSum(float v) {
#pragma unroll
    for (int o = 16; o > 0; o >>= 1) v += __shfl_xor_sync(0xffffffffu, v, o);
    return v;
}

// ---------------- Kernel 1: warp-per-row logsumexp (85% DRAM — unchanged) ----
__global__ void __launch_bounds__(256) lse_kernel(const float* __restrict__ acts,
                                                  const int* __restrict__ labels) {
    const int row  = blockIdx.x * 8 + (threadIdx.x >> 5);
    const int lane = threadIdx.x & 31;

    const int u  = row % UU;
    const int bt = row / UU;
    const int b  = bt / TT;

    const float4* a4 = reinterpret_cast<const float4*>(acts + (size_t)row * VV);
    float4 v[8];
#pragma unroll
    for (int j = 0; j < 8; ++j) v[j] = a4[lane + 32 * j];

    float m = -INFINITY;
#pragma unroll
    for (int j = 0; j < 8; ++j)
        m = fmaxf(m, fmaxf(fmaxf(v[j].x, v[j].y), fmaxf(v[j].z, v[j].w)));
    m = warpMax(m);

    float s = 0.f;
#pragma unroll
    for (int j = 0; j < 8; ++j)
        s += __expf(v[j].x - m) + __expf(v[j].y - m) + __expf(v[j].z - m) + __expf(v[j].w - m);
    s = warpSum(s);
    const float lse = m + __logf(s);

    if (u < UL) {
        const int lab = labels[b * UL + u];
        const int q = lab >> 2, c = lab & 3, jj = q >> 5;
        float cand = 0.f;
#pragma unroll
        for (int j = 0; j < 8; ++j) {
            if (j == jj) {
                float4 f = v[j];
                cand = (c == 0) ? f.x : (c == 1) ? f.y : (c == 2) ? f.z : f.w;
            }
        }
        const float lv = __shfl_sync(0xffffffffu, cand, q & 31);
        if (lane == 0) g_lp_label[bt * UL + u] = lv - lse;
    }
    if (lane == 0) g_lp_blank[row] = v[0].x - lse;
}

__device__ __forceinline__ float lae(float a, float b) {
    float m = fmaxf(a, b);
    float d = fminf(a, b) - m;
    return m + __logf(1.f + __expf(d));
}

// ---------------- Kernel 2: single-warp branch-free wavefront DP -------------
// 1024 threads preload lp tables into padded smem; warps 1..31 exit; warp 0
// runs 318 diagonals entirely in registers. All boundary cases are handled
// with -1e30 sentinels + clamped addresses + SELs: zero branches in the loop.
__global__ void __launch_bounds__(1024) alpha_kernel(const int* __restrict__ act_lens,
                                                     const int* __restrict__ label_lens) {
    extern __shared__ float sm[];
    float* s_blank = sm;                 // TT * SB (cols 0..64 valid)
    float* s_label = sm + TT * SB;       // TT * SB (cols 0..63 valid)

    const int b    = blockIdx.x;
    const int tid  = threadIdx.x;
    const int lane = tid & 31;
    const int wid  = tid >> 5;

    for (int t = wid; t < TT; t += 32) {
        const float* gb = g_lp_blank + ((size_t)b * TT + t) * UU;
        const float* gl = g_lp_label + ((size_t)b * TT + t) * UL;
        s_blank[t * SB + lane]      = gb[lane];
        s_blank[t * SB + 32 + lane] = gb[32 + lane];
        if (lane == 0) s_blank[t * SB + 64] = gb[64];
        s_label[t * SB + lane]      = gl[lane];
        s_label[t * SB + 32 + lane] = gl[32 + lane];
    }
    __syncthreads();
    if (wid != 0) return;

    const int t_tgt = act_lens[b] - 1;
    const int u_tgt = label_lens[b];
    const int d_tgt = t_tgt + u_tgt;

    const int u0 = 2 * lane, u1 = u0 + 1;
    const int ul0 = (lane == 0) ? 0 : (u0 - 1);   // clamped label col for cell 0
    float a0 = 0.f, a1 = 0.f, a2 = 0.f;           // alpha[u0], alpha[u1], alpha[64]
    float tgt = 0.f;

#pragma unroll 2
    for (int d = 1; d < TT + UU - 1; ++d) {
        float pm = __shfl_up_sync(0xffffffffu, a1, 1);   // alpha[u0-1] (prev diag)
        pm = (lane == 0) ? NEG_BIG : pm;

        const int t0 = d - u0, t1 = t0 - 1, t2 = d - 64;

        // cell 0: u = u0
        const int tb0 = min(max(t0 - 1, 0), TT - 1);
        const int tl0 = min(max(t0,     0), TT - 1);
        float bl0 = s_blank[tb0 * SB + u0];
        float lb0 = s_label[tl0 * SB + ul0];
        bl0 = (t0 >= 1) ? bl0 : NEG_BIG;
        const float n0 = lae(a0 + bl0, pm + lb0);

        // cell 1: u = u1
        const int tb1 = min(max(t1 - 1, 0), TT - 1);
        const int tl1 = min(max(t1,     0), TT - 1);
        float bl1 = s_blank[tb1 * SB + u1];
        float lb1 = s_label[tl1 * SB + u0];           // u1-1 == u0
        bl1 = (t1 >= 1) ? bl1 : NEG_BIG;
        const float n1 = lae(a1 + bl1, a0 + lb1);

        // cell 2: u = 64 (broadcast addresses; meaningful only in lane 31)
        const int tb2 = min(max(t2 - 1, 0), TT - 1);
        const int tl2 = min(max(t2,     0), TT - 1);
        float bl2 = s_blank[tb2 * SB + 64];
        float lb2 = s_label[tl2 * SB + 63];
        bl2 = (t2 >= 1) ? bl2 : NEG_BIG;
        const float n2 = lae(a2 + bl2, a1 + lb2);

        // commit (predicated)
        a0 = (t0 >= 0 && t0 < TT) ? n0 : a0;
        a1 = (t1 >= 0 && t1 < TT) ? n1 : a1;
        a2 = (t2 >= 0 && t2 < TT) ? n2 : a2;

        // target capture
        const float pick = (u_tgt == u0) ? n0 : ((u_tgt == u1) ? n1 : n2);
        tgt = (d == d_tgt) ? pick : tgt;
    }

    const int owner = (u_tgt >= 64) ? 31 : (u_tgt >> 1);
    const float av = __shfl_sync(0xffffffffu, tgt, owner);
    if (lane == 0) g_ll[b] = av + s_blank[t_tgt * SB + u_tgt];
}

// ---------------- Kernel 3: finalize ----------------
__global__ void finalize_kernel(float* __restrict__ out) {
    if (threadIdx.x == 0 && blockIdx.x == 0) {
        float s = 0.f;
#pragma unroll
        for (int i = 0; i < BB; ++i) s += g_ll[i];
        out[0] = -s / (float)BB;
    }
}

extern "C" void kernel_launch(void* const* d_in, const int* in_sizes, int n_in,
                              void* d_out, int out_size) {
    const float* acts       = (const float*)d_in[0];
    const int*   labels     = (const int*)d_in[1];
    const int*   act_lens   = (const int*)d_in[2];
    const int*   label_lens = (const int*)d_in[3];
    float* out = (float*)d_out;

    const int smem_alpha = 2 * TT * SB * (int)sizeof(float);
    cudaFuncSetAttribute(alpha_kernel, cudaFuncAttributeMaxDynamicSharedMemorySize, smem_alpha);

    const int rows = BB * TT * UU;                 // 133120 = 8 warps * 16640 blocks
    lse_kernel<<<rows / 8, 256>>>(acts, labels);
    alpha_kernel<<<BB, 1024, smem_alpha>>>(act_lens, label_lens);
    finalize_kernel<<<1, 32>>>(out);
}